// round 1
// baseline (speedup 1.0000x reference)
#include <cuda_runtime.h>
#include <cuda_bf16.h>
#include <cstdint>
#include <cstddef>

#define B_DIM 64
#define N_DIM 1024
#define D_DIM 256
#define T_DIM 13
#define C_DIM 2
#define KX (C_DIM * T_DIM)          // 26
#define NROWS (B_DIM * N_DIM)        // 65536

// c2 = 2*rank - 255 per (row, d), exact in bf16. 32 MB static scratch.
__device__ __nv_bfloat16 g_c2[(size_t)NROWS * D_DIM];

// ---------------------------------------------------------------------------
// K1: conv (26-dot) + LayerNorm(D) + exact stable rank + c2 store.
// One warp per (b,n) row; 8 d-values per lane; counting rank with tie-break
// identical to stable double-argsort: rank_i = #{v_j<v_i} + #{j<i, v_j==v_i}.
// ---------------------------------------------------------------------------
__global__ __launch_bounds__(256) void k1_rank(
    const float* __restrict__ x, const float* __restrict__ w,
    const float* __restrict__ cb, const float* __restrict__ tg,
    const float* __restrict__ tb)
{
    __shared__ float ws[D_DIM * KX];          // conv weights 256x26
    __shared__ float scb[D_DIM], stg[D_DIM], stb[D_DIM];
    __shared__ float sx[8][KX + 2];

    int tid = threadIdx.x;
    for (int i = tid; i < D_DIM * KX; i += 256) ws[i] = w[i];
    scb[tid] = cb[tid]; stg[tid] = tg[tid]; stb[tid] = tb[tid];

    int warp = tid >> 5, lane = tid & 31;
    int row = blockIdx.x * 8 + warp;
    int b = row >> 10, n = row & 1023;

    if (lane < KX) {
        int c = lane / T_DIM, t = lane - c * T_DIM;
        sx[warp][lane] = x[(((size_t)b * C_DIM + c) * N_DIM + n) * T_DIM + t];
    }
    __syncthreads();

    // conv: e[s] for d = s*32 + lane
    float e[8];
#pragma unroll
    for (int s = 0; s < 8; s++) e[s] = scb[s * 32 + lane];
#pragma unroll
    for (int k = 0; k < KX; k++) {
        float xv = sx[warp][k];
#pragma unroll
        for (int s = 0; s < 8; s++) e[s] += xv * ws[(s * 32 + lane) * KX + k];
    }

    // LayerNorm over D=256 (warp allreduce of sum & sumsq)
    float sum = 0.f, sq = 0.f;
#pragma unroll
    for (int s = 0; s < 8; s++) { sum += e[s]; sq += e[s] * e[s]; }
#pragma unroll
    for (int o = 16; o > 0; o >>= 1) {
        sum += __shfl_xor_sync(0xffffffffu, sum, o);
        sq  += __shfl_xor_sync(0xffffffffu, sq,  o);
    }
    float mu = sum * (1.0f / D_DIM);
    float var = sq * (1.0f / D_DIM) - mu * mu;
    float rstd = rsqrtf(var + 1e-5f);

    // sortable uint keys of LN output
    unsigned key[8], kp1[8];
#pragma unroll
    for (int s = 0; s < 8; s++) {
        int d = s * 32 + lane;
        float z = (e[s] - mu) * rstd * stg[d] + stb[d];
        unsigned u = __float_as_uint(z);
        key[s] = (u & 0x80000000u) ? ~u : (u | 0x80000000u);
        kp1[s] = key[s] + 1u;    // for "<=" comparisons (no NaNs -> no overflow)
    }

    // counting rank across the warp's 256 elements (element id = s*32 + lane)
    int cnt[8];
#pragma unroll
    for (int s = 0; s < 8; s++) cnt[s] = 0;

    for (int p = 0; p < 32; p++) {
        unsigned ko[8];
#pragma unroll
        for (int t = 0; t < 8; t++) ko[t] = __shfl_xor_sync(0xffffffffu, key[t], p);
        unsigned q = ((lane ^ p) < lane) ? 1u : 0u;
#pragma unroll
        for (int s = 0; s < 8; s++) {
            unsigned kq = key[s] + q;   // t==s tie resolved by lane order
#pragma unroll
            for (int t = 0; t < 8; t++) {
                unsigned thr = (t < s) ? kp1[s] : ((t == s) ? kq : key[s]);
                cnt[s] += (ko[t] < thr) ? 1 : 0;
            }
        }
    }

    size_t base = (size_t)row * D_DIM;
#pragma unroll
    for (int s = 0; s < 8; s++)
        g_c2[base + s * 32 + lane] = __float2bfloat16((float)(2 * cnt[s] - 255));
}

// ---------------------------------------------------------------------------
// K2: per-batch S = c2 * c2^T (bf16 mma.sync, fp32 accum, exact), epilogue
// adj = |S| * 0.25 / (norm^2 + 1e-8) written straight to d_out.
// CTA tile 128x128, full K=256 resident in smem, 8 warps of 64x32.
// ---------------------------------------------------------------------------
#define LDA 264   // padded row length (bf16 elems) to dodge bank conflicts

__device__ __forceinline__ unsigned sptr(const void* p) {
    return (unsigned)__cvta_generic_to_shared(p);
}
__device__ __forceinline__ void ldm4(unsigned& r0, unsigned& r1, unsigned& r2,
                                     unsigned& r3, unsigned a) {
    asm volatile("ldmatrix.sync.aligned.m8n8.x4.shared.b16 {%0,%1,%2,%3}, [%4];\n"
                 : "=r"(r0), "=r"(r1), "=r"(r2), "=r"(r3) : "r"(a));
}
__device__ __forceinline__ void mma16816(float* d, const unsigned* a,
                                         unsigned b0, unsigned b1) {
    asm volatile(
        "mma.sync.aligned.m16n8k16.row.col.f32.bf16.bf16.f32 "
        "{%0,%1,%2,%3},{%4,%5,%6,%7},{%8,%9},{%0,%1,%2,%3};\n"
        : "+f"(d[0]), "+f"(d[1]), "+f"(d[2]), "+f"(d[3])
        : "r"(a[0]), "r"(a[1]), "r"(a[2]), "r"(a[3]), "r"(b0), "r"(b1));
}

__global__ __launch_bounds__(256) void k2_gemm(float* __restrict__ out)
{
    extern __shared__ __nv_bfloat16 smem[];
    __nv_bfloat16* As = smem;
    __nv_bfloat16* Bs = smem + 128 * LDA;

    int b = blockIdx.z;
    int it = blockIdx.y, jt = blockIdx.x;
    const __nv_bfloat16* Ag = g_c2 + ((size_t)b * N_DIM + it * 128) * D_DIM;
    const __nv_bfloat16* Bg = g_c2 + ((size_t)b * N_DIM + jt * 128) * D_DIM;

    int tid = threadIdx.x;
    for (int i = tid; i < 128 * 32; i += 256) {
        int r = i >> 5, c = i & 31;
        *(uint4*)(As + r * LDA + c * 8) = *(const uint4*)(Ag + r * D_DIM + c * 8);
        *(uint4*)(Bs + r * LDA + c * 8) = *(const uint4*)(Bg + r * D_DIM + c * 8);
    }
    __syncthreads();

    int wid = tid >> 5, lane = tid & 31;
    int wm = (wid >> 2) * 64, wn = (wid & 3) * 32;

    float acc[4][4][4];
#pragma unroll
    for (int mf = 0; mf < 4; mf++)
#pragma unroll
        for (int nf = 0; nf < 4; nf++)
#pragma unroll
            for (int r = 0; r < 4; r++) acc[mf][nf][r] = 0.f;

    unsigned aaddr[4];
#pragma unroll
    for (int mf = 0; mf < 4; mf++)
        aaddr[mf] = sptr(As + (wm + mf * 16 + (lane & 15)) * LDA + ((lane >> 4) << 3));
    unsigned baddr = sptr(Bs + (wn + lane) * LDA);

#pragma unroll 4
    for (int k = 0; k < 256; k += 16) {
        unsigned a[4][4];
#pragma unroll
        for (int mf = 0; mf < 4; mf++)
            ldm4(a[mf][0], a[mf][1], a[mf][2], a[mf][3], aaddr[mf] + 2 * k);
        unsigned bl[4], bh[4];
        ldm4(bl[0], bl[1], bl[2], bl[3], baddr + 2 * k);
        ldm4(bh[0], bh[1], bh[2], bh[3], baddr + 2 * k + 16);
#pragma unroll
        for (int mf = 0; mf < 4; mf++)
#pragma unroll
            for (int nf = 0; nf < 4; nf++)
                mma16816(acc[mf][nf], a[mf], bl[nf], bh[nf]);
    }

    // adj = |S/4| / (norm*norm + 1e-8), norm = sqrt(1398080) (constant)
    const float nn = sqrtf(1398080.0f);
    const float scale = 0.25f / (nn * nn + 1e-8f);

    int i_base = it * 128 + wm + (lane >> 2);
    int j_base = jt * 128 + wn + (lane & 3) * 2;
    float* ob = out + (size_t)b * N_DIM * N_DIM;
#pragma unroll
    for (int mf = 0; mf < 4; mf++)
#pragma unroll
        for (int nf = 0; nf < 4; nf++) {
            int i0 = i_base + mf * 16, j0 = j_base + nf * 8;
            float2 v0, v1;
            v0.x = fabsf(acc[mf][nf][0]) * scale;
            v0.y = fabsf(acc[mf][nf][1]) * scale;
            v1.x = fabsf(acc[mf][nf][2]) * scale;
            v1.y = fabsf(acc[mf][nf][3]) * scale;
            *(float2*)(ob + (size_t)i0 * N_DIM + j0) = v0;
            *(float2*)(ob + (size_t)(i0 + 8) * N_DIM + j0) = v1;
        }
}

// ---------------------------------------------------------------------------
// K3: in-place LayerNorm over last axis (N=1024) + ReLU. One block per row.
// ---------------------------------------------------------------------------
__global__ __launch_bounds__(256) void k3_ln(float* __restrict__ out,
                                             const float* __restrict__ sg,
                                             const float* __restrict__ sb)
{
    size_t row = blockIdx.x;
    float* p = out + row * N_DIM;
    int tid = threadIdx.x;

    float4 v = ((const float4*)p)[tid];
    float s = v.x + v.y + v.z + v.w;
    float q = v.x * v.x + v.y * v.y + v.z * v.z + v.w * v.w;
#pragma unroll
    for (int o = 16; o > 0; o >>= 1) {
        s += __shfl_xor_sync(0xffffffffu, s, o);
        q += __shfl_xor_sync(0xffffffffu, q, o);
    }
    __shared__ float rs[8], rq[8];
    __shared__ float smu, srstd;
    int wid = tid >> 5, lane = tid & 31;
    if (lane == 0) { rs[wid] = s; rq[wid] = q; }
    __syncthreads();
    if (tid == 0) {
        float S = 0.f, Q = 0.f;
#pragma unroll
        for (int i = 0; i < 8; i++) { S += rs[i]; Q += rq[i]; }
        float mu = S * (1.0f / N_DIM);
        float var = Q * (1.0f / N_DIM) - mu * mu;
        smu = mu;
        srstd = rsqrtf(var + 1e-5f);
    }
    __syncthreads();
    float mu = smu, rstd = srstd;

    float4 g = ((const float4*)sg)[tid];
    float4 bb = ((const float4*)sb)[tid];
    float4 r;
    r.x = fmaxf((v.x - mu) * rstd * g.x + bb.x, 0.0f);
    r.y = fmaxf((v.y - mu) * rstd * g.y + bb.y, 0.0f);
    r.z = fmaxf((v.z - mu) * rstd * g.z + bb.z, 0.0f);
    r.w = fmaxf((v.w - mu) * rstd * g.w + bb.w, 0.0f);
    ((float4*)p)[tid] = r;
}

// ---------------------------------------------------------------------------
extern "C" void kernel_launch(void* const* d_in, const int* in_sizes, int n_in,
                              void* d_out, int out_size)
{
    (void)in_sizes; (void)n_in; (void)out_size;
    const float* x        = (const float*)d_in[0];
    const float* conv_w   = (const float*)d_in[1];
    const float* conv_b   = (const float*)d_in[2];
    const float* time_g   = (const float*)d_in[3];
    const float* time_b   = (const float*)d_in[4];
    const float* static_g = (const float*)d_in[5];
    const float* static_b = (const float*)d_in[6];
    float* out = (float*)d_out;

    k1_rank<<<NROWS / 8, 256>>>(x, conv_w, conv_b, time_g, time_b);

    size_t smem_bytes = 2 * 128 * LDA * sizeof(__nv_bfloat16);
    cudaFuncSetAttribute(k2_gemm, cudaFuncAttributeMaxDynamicSharedMemorySize,
                         (int)smem_bytes);
    dim3 g2(8, 8, 64);
    k2_gemm<<<g2, 256, smem_bytes>>>(out);

    k3_ln<<<NROWS, 256>>>(out, static_g, static_b);
}

// round 2
// speedup vs baseline: 1.7335x; 1.7335x over previous
#include <cuda_runtime.h>
#include <cuda_bf16.h>
#include <cstdint>
#include <cstddef>

#define B_DIM 64
#define N_DIM 1024
#define D_DIM 256
#define T_DIM 13
#define C_DIM 2
#define KX (C_DIM * T_DIM)          // 26
#define NROWS (B_DIM * N_DIM)        // 65536

// c2 = 2*rank - 255 per (row, d), exact in bf16. 32 MB static scratch.
__device__ __nv_bfloat16 g_c2[(size_t)NROWS * D_DIM];

// ---------------------------------------------------------------------------
// K1: conv (26-dot) + LayerNorm(D) + stable rank via warp bitonic sort + c2.
// One warp per (b,n) row; 8 items per lane; items are 64-bit composites
// (sortable_key<<8)|d, so sort order == stable argsort order and
// rank(d) == final sorted position.
// ---------------------------------------------------------------------------
__global__ __launch_bounds__(256) void k1_rank(
    const float* __restrict__ x, const float* __restrict__ w,
    const float* __restrict__ cb, const float* __restrict__ tg,
    const float* __restrict__ tb)
{
    __shared__ float ws[D_DIM * KX];          // conv weights 256x26
    __shared__ float scb[D_DIM], stg[D_DIM], stb[D_DIM];
    __shared__ float sx[8][KX + 2];
    __shared__ __nv_bfloat16 sc[8][256];      // rank scatter staging

    int tid = threadIdx.x;
    for (int i = tid; i < D_DIM * KX; i += 256) ws[i] = w[i];
    scb[tid] = cb[tid]; stg[tid] = tg[tid]; stb[tid] = tb[tid];

    int warp = tid >> 5, lane = tid & 31;
    int row = blockIdx.x * 8 + warp;
    int b = row >> 10, n = row & 1023;

    if (lane < KX) {
        int c = lane / T_DIM, t = lane - c * T_DIM;
        sx[warp][lane] = x[(((size_t)b * C_DIM + c) * N_DIM + n) * T_DIM + t];
    }
    __syncthreads();

    // conv: e[s] for d = s*32 + lane
    float e[8];
#pragma unroll
    for (int s = 0; s < 8; s++) e[s] = scb[s * 32 + lane];
#pragma unroll
    for (int k = 0; k < KX; k++) {
        float xv = sx[warp][k];
#pragma unroll
        for (int s = 0; s < 8; s++) e[s] += xv * ws[(s * 32 + lane) * KX + k];
    }

    // LayerNorm over D=256 (warp allreduce of sum & sumsq)
    float sum = 0.f, sq = 0.f;
#pragma unroll
    for (int s = 0; s < 8; s++) { sum += e[s]; sq += e[s] * e[s]; }
#pragma unroll
    for (int o = 16; o > 0; o >>= 1) {
        sum += __shfl_xor_sync(0xffffffffu, sum, o);
        sq  += __shfl_xor_sync(0xffffffffu, sq,  o);
    }
    float mu = sum * (1.0f / D_DIM);
    float var = sq * (1.0f / D_DIM) - mu * mu;
    float rstd = rsqrtf(var + 1e-5f);

    // 64-bit sort items: (monotonic uint key << 8) | original index d
    unsigned long long item[8];
#pragma unroll
    for (int s = 0; s < 8; s++) {
        int d = s * 32 + lane;
        float z = (e[s] - mu) * rstd * stg[d] + stb[d];
        unsigned u = __float_as_uint(z);
        unsigned key = (u & 0x80000000u) ? ~u : (u | 0x80000000u);
        item[s] = ((unsigned long long)key << 8) | (unsigned)d;
    }

    // Bitonic sort of 256 items; position p = lane*8 + s.
#pragma unroll
    for (int ks = 1; ks <= 8; ks++) {
        const int k = 1 << ks;
#pragma unroll
        for (int js = ks - 1; js >= 0; js--) {
            const int j = 1 << js;
            if (j >= 8) {
                const int jl = j >> 3;                       // lane distance
                bool up = ((lane & (k >> 3)) == 0);          // p&k (lane bit)
                bool keepmin = (((lane & jl) == 0) == up);
#pragma unroll
                for (int s = 0; s < 8; s++) {
                    unsigned long long o =
                        __shfl_xor_sync(0xffffffffu, item[s], jl);
                    unsigned long long mn = item[s] < o ? item[s] : o;
                    unsigned long long mx = item[s] < o ? o : item[s];
                    item[s] = keepmin ? mn : mx;
                }
            } else {
#pragma unroll
                for (int s = 0; s < 8; s++) {
                    if ((s & j) == 0) {
                        int a = s, bb2 = s | j;
                        int p = (lane << 3) | a;
                        bool up = ((p & k) == 0);
                        unsigned long long xv = item[a], yv = item[bb2];
                        unsigned long long mn = xv < yv ? xv : yv;
                        unsigned long long mx = xv < yv ? yv : xv;
                        item[a]   = up ? mn : mx;
                        item[bb2] = up ? mx : mn;
                    }
                }
            }
        }
    }

    // Scatter: item at position p has rank p; c2 = 2p - 255.
#pragma unroll
    for (int s = 0; s < 8; s++) {
        int d = (int)(item[s] & 0xFF);
        int p = (lane << 3) | s;
        sc[warp][d] = __float2bfloat16((float)(2 * p - 255));
    }
    __syncwarp();

    size_t base = (size_t)row * D_DIM;
    uint4 v = ((const uint4*)sc[warp])[lane];       // 8 bf16 per lane
    *(uint4*)(g_c2 + base + lane * 8) = v;
}

// ---------------------------------------------------------------------------
// K2: per-batch S = c2 * c2^T (bf16 mma.sync, fp32 accum, exact), epilogue
// adj = |S| * 0.25 / (norm^2 + 1e-8) written straight to d_out.
// CTA tile 128x128, full K=256 resident in smem, 8 warps of 64x32.
// ---------------------------------------------------------------------------
#define LDA 264   // padded row length (bf16 elems) to dodge bank conflicts

__device__ __forceinline__ unsigned sptr(const void* p) {
    return (unsigned)__cvta_generic_to_shared(p);
}
__device__ __forceinline__ void ldm4(unsigned& r0, unsigned& r1, unsigned& r2,
                                     unsigned& r3, unsigned a) {
    asm volatile("ldmatrix.sync.aligned.m8n8.x4.shared.b16 {%0,%1,%2,%3}, [%4];\n"
                 : "=r"(r0), "=r"(r1), "=r"(r2), "=r"(r3) : "r"(a));
}
__device__ __forceinline__ void mma16816(float* d, const unsigned* a,
                                         unsigned b0, unsigned b1) {
    asm volatile(
        "mma.sync.aligned.m16n8k16.row.col.f32.bf16.bf16.f32 "
        "{%0,%1,%2,%3},{%4,%5,%6,%7},{%8,%9},{%0,%1,%2,%3};\n"
        : "+f"(d[0]), "+f"(d[1]), "+f"(d[2]), "+f"(d[3])
        : "r"(a[0]), "r"(a[1]), "r"(a[2]), "r"(a[3]), "r"(b0), "r"(b1));
}

__global__ __launch_bounds__(256) void k2_gemm(float* __restrict__ out)
{
    extern __shared__ __nv_bfloat16 smem[];
    __nv_bfloat16* As = smem;
    __nv_bfloat16* Bs = smem + 128 * LDA;

    int b = blockIdx.z;
    int it = blockIdx.y, jt = blockIdx.x;
    const __nv_bfloat16* Ag = g_c2 + ((size_t)b * N_DIM + it * 128) * D_DIM;
    const __nv_bfloat16* Bg = g_c2 + ((size_t)b * N_DIM + jt * 128) * D_DIM;

    int tid = threadIdx.x;
    for (int i = tid; i < 128 * 32; i += 256) {
        int r = i >> 5, c = i & 31;
        *(uint4*)(As + r * LDA + c * 8) = *(const uint4*)(Ag + r * D_DIM + c * 8);
        *(uint4*)(Bs + r * LDA + c * 8) = *(const uint4*)(Bg + r * D_DIM + c * 8);
    }
    __syncthreads();

    int wid = tid >> 5, lane = tid & 31;
    int wm = (wid >> 2) * 64, wn = (wid & 3) * 32;

    float acc[4][4][4];
#pragma unroll
    for (int mf = 0; mf < 4; mf++)
#pragma unroll
        for (int nf = 0; nf < 4; nf++)
#pragma unroll
            for (int r = 0; r < 4; r++) acc[mf][nf][r] = 0.f;

    unsigned aaddr[4];
#pragma unroll
    for (int mf = 0; mf < 4; mf++)
        aaddr[mf] = sptr(As + (wm + mf * 16 + (lane & 15)) * LDA + ((lane >> 4) << 3));
    unsigned baddr = sptr(Bs + (wn + lane) * LDA);

#pragma unroll 4
    for (int k = 0; k < 256; k += 16) {
        unsigned a[4][4];
#pragma unroll
        for (int mf = 0; mf < 4; mf++)
            ldm4(a[mf][0], a[mf][1], a[mf][2], a[mf][3], aaddr[mf] + 2 * k);
        unsigned bl[4], bh[4];
        ldm4(bl[0], bl[1], bl[2], bl[3], baddr + 2 * k);
        ldm4(bh[0], bh[1], bh[2], bh[3], baddr + 2 * k + 16);
#pragma unroll
        for (int mf = 0; mf < 4; mf++)
#pragma unroll
            for (int nf = 0; nf < 4; nf++)
                mma16816(acc[mf][nf], a[mf], bl[nf], bh[nf]);
    }

    // adj = |S/4| / (norm^2 + 1e-8), norm = sqrt(1398080) (constant)
    const float nn = sqrtf(1398080.0f);
    const float scale = 0.25f / (nn * nn + 1e-8f);

    int i_base = it * 128 + wm + (lane >> 2);
    int j_base = jt * 128 + wn + (lane & 3) * 2;
    float* ob = out + (size_t)b * N_DIM * N_DIM;
#pragma unroll
    for (int mf = 0; mf < 4; mf++)
#pragma unroll
        for (int nf = 0; nf < 4; nf++) {
            int i0 = i_base + mf * 16, j0 = j_base + nf * 8;
            float2 v0, v1;
            v0.x = fabsf(acc[mf][nf][0]) * scale;
            v0.y = fabsf(acc[mf][nf][1]) * scale;
            v1.x = fabsf(acc[mf][nf][2]) * scale;
            v1.y = fabsf(acc[mf][nf][3]) * scale;
            *(float2*)(ob + (size_t)i0 * N_DIM + j0) = v0;
            *(float2*)(ob + (size_t)(i0 + 8) * N_DIM + j0) = v1;
        }
}

// ---------------------------------------------------------------------------
// K3: in-place LayerNorm over last axis (N=1024) + ReLU. One block per row.
// ---------------------------------------------------------------------------
__global__ __launch_bounds__(256) void k3_ln(float* __restrict__ out,
                                             const float* __restrict__ sg,
                                             const float* __restrict__ sb)
{
    size_t row = blockIdx.x;
    float* p = out + row * N_DIM;
    int tid = threadIdx.x;

    float4 v = ((const float4*)p)[tid];
    float s = v.x + v.y + v.z + v.w;
    float q = v.x * v.x + v.y * v.y + v.z * v.z + v.w * v.w;
#pragma unroll
    for (int o = 16; o > 0; o >>= 1) {
        s += __shfl_xor_sync(0xffffffffu, s, o);
        q += __shfl_xor_sync(0xffffffffu, q, o);
    }
    __shared__ float rs[8], rq[8];
    __shared__ float smu, srstd;
    int wid = tid >> 5, lane = tid & 31;
    if (lane == 0) { rs[wid] = s; rq[wid] = q; }
    __syncthreads();
    if (tid == 0) {
        float S = 0.f, Q = 0.f;
#pragma unroll
        for (int i = 0; i < 8; i++) { S += rs[i]; Q += rq[i]; }
        float mu = S * (1.0f / N_DIM);
        float var = Q * (1.0f / N_DIM) - mu * mu;
        smu = mu;
        srstd = rsqrtf(var + 1e-5f);
    }
    __syncthreads();
    float mu = smu, rstd = srstd;

    float4 g = ((const float4*)sg)[tid];
    float4 bb = ((const float4*)sb)[tid];
    float4 r;
    r.x = fmaxf((v.x - mu) * rstd * g.x + bb.x, 0.0f);
    r.y = fmaxf((v.y - mu) * rstd * g.y + bb.y, 0.0f);
    r.z = fmaxf((v.z - mu) * rstd * g.z + bb.z, 0.0f);
    r.w = fmaxf((v.w - mu) * rstd * g.w + bb.w, 0.0f);
    ((float4*)p)[tid] = r;
}

// ---------------------------------------------------------------------------
extern "C" void kernel_launch(void* const* d_in, const int* in_sizes, int n_in,
                              void* d_out, int out_size)
{
    (void)in_sizes; (void)n_in; (void)out_size;
    const float* x        = (const float*)d_in[0];
    const float* conv_w   = (const float*)d_in[1];
    const float* conv_b   = (const float*)d_in[2];
    const float* time_g   = (const float*)d_in[3];
    const float* time_b   = (const float*)d_in[4];
    const float* static_g = (const float*)d_in[5];
    const float* static_b = (const float*)d_in[6];
    float* out = (float*)d_out;

    k1_rank<<<NROWS / 8, 256>>>(x, conv_w, conv_b, time_g, time_b);

    size_t smem_bytes = 2 * 128 * LDA * sizeof(__nv_bfloat16);
    cudaFuncSetAttribute(k2_gemm, cudaFuncAttributeMaxDynamicSharedMemorySize,
                         (int)smem_bytes);
    dim3 g2(8, 8, 64);
    k2_gemm<<<g2, 256, smem_bytes>>>(out);

    k3_ln<<<NROWS, 256>>>(out, static_g, static_b);
}

// round 3
// speedup vs baseline: 2.2508x; 1.2984x over previous
#include <cuda_runtime.h>
#include <cuda_bf16.h>
#include <cstdint>
#include <cstddef>

#define B_DIM 64
#define N_DIM 1024
#define D_DIM 256
#define T_DIM 13
#define C_DIM 2
#define KX (C_DIM * T_DIM)          // 26
#define NROWS (B_DIM * N_DIM)        // 65536

// c2 = 2*rank - 255 per (row, d), exact in bf16. 32 MB static scratch.
__device__ __nv_bfloat16 g_c2[(size_t)NROWS * D_DIM];

// ---------------------------------------------------------------------------
// K1: conv (26-dot) + LayerNorm(D) + rank via 32-bit warp bitonic sort +
// per-warp smem binary search (exact lower_bound, keys unique w.h.p.).
// One warp per (b,n) row; 8 items per lane.
// ---------------------------------------------------------------------------
__global__ __launch_bounds__(256) void k1_rank(
    const float* __restrict__ x, const float* __restrict__ w,
    const float* __restrict__ cb, const float* __restrict__ tg,
    const float* __restrict__ tb)
{
    __shared__ float wst[KX * D_DIM];         // conv weights transposed [k][d]
    __shared__ float scb[D_DIM], stg[D_DIM], stb[D_DIM];
    __shared__ float sx[8][KX + 2];
    __shared__ unsigned sortbuf[8][256];      // sorted keys per warp

    int tid = threadIdx.x;
    // transpose weights into smem: wst[k*256+d] = w[d*26+k]
#pragma unroll
    for (int k = 0; k < KX; k++) wst[k * D_DIM + tid] = w[tid * KX + k];
    scb[tid] = cb[tid]; stg[tid] = tg[tid]; stb[tid] = tb[tid];

    int warp = tid >> 5, lane = tid & 31;
    int row = blockIdx.x * 8 + warp;
    int b = row >> 10, n = row & 1023;

    if (lane < KX) {
        int c = lane / T_DIM, t = lane - c * T_DIM;
        sx[warp][lane] = x[(((size_t)b * C_DIM + c) * N_DIM + n) * T_DIM + t];
    }
    __syncthreads();

    // conv: e[s] for d = s*32 + lane  (conflict-free LDS on wst)
    float e[8];
#pragma unroll
    for (int s = 0; s < 8; s++) e[s] = scb[s * 32 + lane];
#pragma unroll
    for (int k = 0; k < KX; k++) {
        float xv = sx[warp][k];
#pragma unroll
        for (int s = 0; s < 8; s++) e[s] += xv * wst[k * D_DIM + s * 32 + lane];
    }

    // LayerNorm over D=256 (warp allreduce of sum & sumsq)
    float sum = 0.f, sq = 0.f;
#pragma unroll
    for (int s = 0; s < 8; s++) { sum += e[s]; sq += e[s] * e[s]; }
#pragma unroll
    for (int o = 16; o > 0; o >>= 1) {
        sum += __shfl_xor_sync(0xffffffffu, sum, o);
        sq  += __shfl_xor_sync(0xffffffffu, sq,  o);
    }
    float mu = sum * (1.0f / D_DIM);
    float var = sq * (1.0f / D_DIM) - mu * mu;
    float rstd = rsqrtf(var + 1e-5f);

    // 32-bit monotonic keys of LN output; keep originals for rank lookup
    unsigned item[8], orig[8];
#pragma unroll
    for (int s = 0; s < 8; s++) {
        int d = s * 32 + lane;
        float z = (e[s] - mu) * rstd * stg[d] + stb[d];
        unsigned u = __float_as_uint(z);
        unsigned key = (u & 0x80000000u) ? ~u : (u | 0x80000000u);
        item[s] = key;
        orig[s] = key;
    }

    // Bitonic sort of 256 u32 keys; position p = lane*8 + s.
#pragma unroll
    for (int ks = 1; ks <= 8; ks++) {
        const int k = 1 << ks;
#pragma unroll
        for (int js = ks - 1; js >= 0; js--) {
            const int j = 1 << js;
            if (j >= 8) {
                const int jl = j >> 3;                       // lane distance
                bool up = ((lane & (k >> 3)) == 0);
                bool keepmin = (((lane & jl) == 0) == up);
#pragma unroll
                for (int s = 0; s < 8; s++) {
                    unsigned o = __shfl_xor_sync(0xffffffffu, item[s], jl);
                    unsigned mn = item[s] < o ? item[s] : o;
                    unsigned mx = item[s] < o ? o : item[s];
                    item[s] = keepmin ? mn : mx;
                }
            } else {
#pragma unroll
                for (int s = 0; s < 8; s++) {
                    if ((s & j) == 0) {
                        int a = s, bb2 = s | j;
                        int p = (lane << 3) | a;
                        bool up = ((p & k) == 0);
                        unsigned xv = item[a], yv = item[bb2];
                        unsigned mn = xv < yv ? xv : yv;
                        unsigned mx = xv < yv ? yv : xv;
                        item[a]   = up ? mn : mx;
                        item[bb2] = up ? mx : mn;
                    }
                }
            }
        }
    }

    // Publish sorted keys: sortbuf[warp][lane*8+s]
    unsigned* sbuf = sortbuf[warp];
    {
        uint4 v0 = make_uint4(item[0], item[1], item[2], item[3]);
        uint4 v1 = make_uint4(item[4], item[5], item[6], item[7]);
        ((uint4*)sbuf)[lane * 2 + 0] = v0;
        ((uint4*)sbuf)[lane * 2 + 1] = v1;
    }
    __syncwarp();

    // rank = lower_bound position (keys unique): 8-step binary search, ILP x8
    unsigned lo[8];
#pragma unroll
    for (int s = 0; s < 8; s++) lo[s] = 0;
#pragma unroll
    for (int wstep = 128; wstep > 0; wstep >>= 1) {
#pragma unroll
        for (int s = 0; s < 8; s++)
            if (sbuf[lo[s] + wstep - 1] < orig[s]) lo[s] += wstep;
    }
    __syncwarp();   // done reading sbuf; reuse it as bf16 staging

    __nv_bfloat16* stage = (__nv_bfloat16*)sbuf;
#pragma unroll
    for (int s = 0; s < 8; s++)
        stage[s * 32 + lane] = __float2bfloat16((float)(2 * (int)lo[s] - 255));
    __syncwarp();

    size_t base = (size_t)row * D_DIM;
    uint4 v = ((const uint4*)stage)[lane];          // 8 bf16 per lane
    *(uint4*)(g_c2 + base + lane * 8) = v;
}

// ---------------------------------------------------------------------------
// K2: per-batch S = c2 * c2^T (bf16 mma.sync, fp32 accum, exact).
// Symmetry: only tiles jt >= it computed (36 of 64); mirror tile written via
// smem transpose staging. Epilogue: adj = |S| * 0.25 / (norm^2 + 1e-8).
// CTA tile 128x128, full K=256 in smem, 8 warps of 64x32.
// ---------------------------------------------------------------------------
#define LDA 264   // padded row length (bf16 elems) to dodge bank conflicts
#define TSP 132   // transpose staging pitch (floats)

__constant__ int IT_MAP[36] = {0,0,0,0,0,0,0,0, 1,1,1,1,1,1,1, 2,2,2,2,2,2,
                               3,3,3,3,3, 4,4,4,4, 5,5,5, 6,6, 7};
__constant__ int JT_MAP[36] = {0,1,2,3,4,5,6,7, 1,2,3,4,5,6,7, 2,3,4,5,6,7,
                               3,4,5,6,7, 4,5,6,7, 5,6,7, 6,7, 7};

__device__ __forceinline__ unsigned sptr(const void* p) {
    return (unsigned)__cvta_generic_to_shared(p);
}
__device__ __forceinline__ void ldm4(unsigned& r0, unsigned& r1, unsigned& r2,
                                     unsigned& r3, unsigned a) {
    asm volatile("ldmatrix.sync.aligned.m8n8.x4.shared.b16 {%0,%1,%2,%3}, [%4];\n"
                 : "=r"(r0), "=r"(r1), "=r"(r2), "=r"(r3) : "r"(a));
}
__device__ __forceinline__ void mma16816(float* d, const unsigned* a,
                                         unsigned b0, unsigned b1) {
    asm volatile(
        "mma.sync.aligned.m16n8k16.row.col.f32.bf16.bf16.f32 "
        "{%0,%1,%2,%3},{%4,%5,%6,%7},{%8,%9},{%0,%1,%2,%3};\n"
        : "+f"(d[0]), "+f"(d[1]), "+f"(d[2]), "+f"(d[3])
        : "r"(a[0]), "r"(a[1]), "r"(a[2]), "r"(a[3]), "r"(b0), "r"(b1));
}

__global__ __launch_bounds__(256) void k2_gemm(float* __restrict__ out)
{
    extern __shared__ __nv_bfloat16 smem[];
    __nv_bfloat16* As = smem;
    __nv_bfloat16* Bs = smem + 128 * LDA;

    int b = blockIdx.z;
    int tt = blockIdx.x;
    int it = IT_MAP[tt], jt = JT_MAP[tt];
    const __nv_bfloat16* Ag = g_c2 + ((size_t)b * N_DIM + it * 128) * D_DIM;
    const __nv_bfloat16* Bg = g_c2 + ((size_t)b * N_DIM + jt * 128) * D_DIM;

    int tid = threadIdx.x;
    for (int i = tid; i < 128 * 32; i += 256) {
        int r = i >> 5, c = i & 31;
        *(uint4*)(As + r * LDA + c * 8) = *(const uint4*)(Ag + r * D_DIM + c * 8);
        *(uint4*)(Bs + r * LDA + c * 8) = *(const uint4*)(Bg + r * D_DIM + c * 8);
    }
    __syncthreads();

    int wid = tid >> 5, lane = tid & 31;
    int wm = (wid >> 2) * 64, wn = (wid & 3) * 32;

    float acc[4][4][4];
#pragma unroll
    for (int mf = 0; mf < 4; mf++)
#pragma unroll
        for (int nf = 0; nf < 4; nf++)
#pragma unroll
            for (int r = 0; r < 4; r++) acc[mf][nf][r] = 0.f;

    unsigned aaddr[4];
#pragma unroll
    for (int mf = 0; mf < 4; mf++)
        aaddr[mf] = sptr(As + (wm + mf * 16 + (lane & 15)) * LDA + ((lane >> 4) << 3));
    unsigned baddr = sptr(Bs + (wn + lane) * LDA);

#pragma unroll 4
    for (int k = 0; k < 256; k += 16) {
        unsigned a[4][4];
#pragma unroll
        for (int mf = 0; mf < 4; mf++)
            ldm4(a[mf][0], a[mf][1], a[mf][2], a[mf][3], aaddr[mf] + 2 * k);
        unsigned bl[4], bh[4];
        ldm4(bl[0], bl[1], bl[2], bl[3], baddr + 2 * k);
        ldm4(bh[0], bh[1], bh[2], bh[3], baddr + 2 * k + 16);
#pragma unroll
        for (int mf = 0; mf < 4; mf++)
#pragma unroll
            for (int nf = 0; nf < 4; nf++)
                mma16816(acc[mf][nf], a[mf], bl[nf], bh[nf]);
    }

    // adj = |S/4| / (norm^2 + 1e-8), norm = sqrt(1398080) (constant)
    const float nn = sqrtf(1398080.0f);
    const float scale = 0.25f / (nn * nn + 1e-8f);

    int il = wm + (lane >> 2);          // local i of fragment row 0
    int jl = wn + (lane & 3) * 2;       // local j of fragment col 0
    float* ob = out + (size_t)b * N_DIM * N_DIM;

    // scaled absolute values
    float vabs[4][4][4];
#pragma unroll
    for (int mf = 0; mf < 4; mf++)
#pragma unroll
        for (int nf = 0; nf < 4; nf++)
#pragma unroll
            for (int r = 0; r < 4; r++)
                vabs[mf][nf][r] = fabsf(acc[mf][nf][r]) * scale;

    // direct (upper) tile write, coalesced
#pragma unroll
    for (int mf = 0; mf < 4; mf++)
#pragma unroll
        for (int nf = 0; nf < 4; nf++) {
            int i0 = it * 128 + il + mf * 16, j0 = jt * 128 + jl + nf * 8;
            float2 v0, v1;
            v0.x = vabs[mf][nf][0]; v0.y = vabs[mf][nf][1];
            v1.x = vabs[mf][nf][2]; v1.y = vabs[mf][nf][3];
            *(float2*)(ob + (size_t)i0 * N_DIM + j0) = v0;
            *(float2*)(ob + (size_t)(i0 + 8) * N_DIM + j0) = v1;
        }

    if (it == jt) return;

    // mirror tile: stage transposed in smem (pitch 132 -> conflict-free)
    __syncthreads();            // all warps done reading As/Bs
    float* ts = (float*)smem;   // ts[j*TSP + i] holds adj(i,j)
#pragma unroll
    for (int mf = 0; mf < 4; mf++)
#pragma unroll
        for (int nf = 0; nf < 4; nf++) {
            int i0 = il + mf * 16, j0 = jl + nf * 8;
            ts[(j0    ) * TSP + i0    ] = vabs[mf][nf][0];
            ts[(j0 + 1) * TSP + i0    ] = vabs[mf][nf][1];
            ts[(j0    ) * TSP + i0 + 8] = vabs[mf][nf][2];
            ts[(j0 + 1) * TSP + i0 + 8] = vabs[mf][nf][3];
        }
    __syncthreads();

    // write lower tile (jt,it): row r (j-local), cols i-local, coalesced
#pragma unroll
    for (int pass = 0; pass < 16; pass++) {
        int r = (tid >> 5) + pass * 8;
        int c4 = (tid & 31) * 4;
        float4 v = *(float4*)&ts[r * TSP + c4];
        *(float4*)(ob + (size_t)(jt * 128 + r) * N_DIM + it * 128 + c4) = v;
    }
}

// ---------------------------------------------------------------------------
// K3: in-place LayerNorm over last axis (N=1024) + ReLU. One block per row.
// ---------------------------------------------------------------------------
__global__ __launch_bounds__(256) void k3_ln(float* __restrict__ out,
                                             const float* __restrict__ sg,
                                             const float* __restrict__ sb)
{
    size_t row = blockIdx.x;
    float* p = out + row * N_DIM;
    int tid = threadIdx.x;

    float4 v = ((const float4*)p)[tid];
    float s = v.x + v.y + v.z + v.w;
    float q = v.x * v.x + v.y * v.y + v.z * v.z + v.w * v.w;
#pragma unroll
    for (int o = 16; o > 0; o >>= 1) {
        s += __shfl_xor_sync(0xffffffffu, s, o);
        q += __shfl_xor_sync(0xffffffffu, q, o);
    }
    __shared__ float rs[8], rq[8];
    __shared__ float smu, srstd;
    int wid = tid >> 5, lane = tid & 31;
    if (lane == 0) { rs[wid] = s; rq[wid] = q; }
    __syncthreads();
    if (tid == 0) {
        float S = 0.f, Q = 0.f;
#pragma unroll
        for (int i = 0; i < 8; i++) { S += rs[i]; Q += rq[i]; }
        float mu = S * (1.0f / N_DIM);
        float var = Q * (1.0f / N_DIM) - mu * mu;
        smu = mu;
        srstd = rsqrtf(var + 1e-5f);
    }
    __syncthreads();
    float mu = smu, rstd = srstd;

    float4 g = ((const float4*)sg)[tid];
    float4 bb = ((const float4*)sb)[tid];
    float4 r;
    r.x = fmaxf((v.x - mu) * rstd * g.x + bb.x, 0.0f);
    r.y = fmaxf((v.y - mu) * rstd * g.y + bb.y, 0.0f);
    r.z = fmaxf((v.z - mu) * rstd * g.z + bb.z, 0.0f);
    r.w = fmaxf((v.w - mu) * rstd * g.w + bb.w, 0.0f);
    ((float4*)p)[tid] = r;
}

// ---------------------------------------------------------------------------
extern "C" void kernel_launch(void* const* d_in, const int* in_sizes, int n_in,
                              void* d_out, int out_size)
{
    (void)in_sizes; (void)n_in; (void)out_size;
    const float* x        = (const float*)d_in[0];
    const float* conv_w   = (const float*)d_in[1];
    const float* conv_b   = (const float*)d_in[2];
    const float* time_g   = (const float*)d_in[3];
    const float* time_b   = (const float*)d_in[4];
    const float* static_g = (const float*)d_in[5];
    const float* static_b = (const float*)d_in[6];
    float* out = (float*)d_out;

    k1_rank<<<NROWS / 8, 256>>>(x, conv_w, conv_b, time_g, time_b);

    size_t smem_bytes = 2 * 128 * LDA * sizeof(__nv_bfloat16);
    cudaFuncSetAttribute(k2_gemm, cudaFuncAttributeMaxDynamicSharedMemorySize,
                         (int)smem_bytes);
    dim3 g2(36, 1, 64);
    k2_gemm<<<g2, 256, smem_bytes>>>(out);

    k3_ln<<<NROWS, 256>>>(out, static_g, static_b);
}

// round 4
// speedup vs baseline: 3.0571x; 1.3582x over previous
#include <cuda_runtime.h>
#include <cuda_bf16.h>
#include <cstdint>
#include <cstddef>

#define B_DIM 64
#define N_DIM 1024
#define D_DIM 256
#define T_DIM 13
#define C_DIM 2
#define KX (C_DIM * T_DIM)          // 26
#define NROWS (B_DIM * N_DIM)        // 65536

// c2 = 2*rank - 255 per (row, d), exact in bf16. 32 MB static scratch.
__device__ __nv_bfloat16 g_c2[(size_t)NROWS * D_DIM];

// skewed index for per-warp sorted-key buffer: kills bank conflicts in the
// binary search (raw addresses are congruent mod 32 at every search step).
#define SKW(i) ((i) + ((i) >> 5))
#define SBUF_LEN 264                 // 256 + 8 skew slack

// ---------------------------------------------------------------------------
// K1: conv (26-dot) + LayerNorm(D) + rank via 32-bit warp bitonic sort +
// per-warp skewed-smem binary search (exact lower_bound, keys unique w.h.p.).
// One warp per (b,n) row; 8 items per lane.
// ---------------------------------------------------------------------------
__global__ __launch_bounds__(256) void k1_rank(
    const float* __restrict__ x, const float* __restrict__ w,
    const float* __restrict__ cb, const float* __restrict__ tg,
    const float* __restrict__ tb)
{
    __shared__ float wst[KX * D_DIM];         // conv weights transposed [k][d]
    __shared__ float scb[D_DIM], stg[D_DIM], stb[D_DIM];
    __shared__ float sx[8][KX + 2];
    __shared__ unsigned sortbuf[8][SBUF_LEN]; // skewed sorted keys per warp

    int tid = threadIdx.x;
#pragma unroll
    for (int k = 0; k < KX; k++) wst[k * D_DIM + tid] = w[tid * KX + k];
    scb[tid] = cb[tid]; stg[tid] = tg[tid]; stb[tid] = tb[tid];

    int warp = tid >> 5, lane = tid & 31;
    int row = blockIdx.x * 8 + warp;
    int b = row >> 10, n = row & 1023;

    if (lane < KX) {
        int c = lane / T_DIM, t = lane - c * T_DIM;
        sx[warp][lane] = x[(((size_t)b * C_DIM + c) * N_DIM + n) * T_DIM + t];
    }
    __syncthreads();

    // conv: e[s] for d = s*32 + lane  (conflict-free LDS on wst)
    float e[8];
#pragma unroll
    for (int s = 0; s < 8; s++) e[s] = scb[s * 32 + lane];
#pragma unroll
    for (int k = 0; k < KX; k++) {
        float xv = sx[warp][k];
#pragma unroll
        for (int s = 0; s < 8; s++) e[s] += xv * wst[k * D_DIM + s * 32 + lane];
    }

    // LayerNorm over D=256 (warp allreduce of sum & sumsq)
    float sum = 0.f, sq = 0.f;
#pragma unroll
    for (int s = 0; s < 8; s++) { sum += e[s]; sq += e[s] * e[s]; }
#pragma unroll
    for (int o = 16; o > 0; o >>= 1) {
        sum += __shfl_xor_sync(0xffffffffu, sum, o);
        sq  += __shfl_xor_sync(0xffffffffu, sq,  o);
    }
    float mu = sum * (1.0f / D_DIM);
    float var = sq * (1.0f / D_DIM) - mu * mu;
    float rstd = rsqrtf(var + 1e-5f);

    // 32-bit monotonic keys of LN output; keep originals for rank lookup
    unsigned item[8], orig[8];
#pragma unroll
    for (int s = 0; s < 8; s++) {
        int d = s * 32 + lane;
        float z = (e[s] - mu) * rstd * stg[d] + stb[d];
        unsigned u = __float_as_uint(z);
        unsigned key = (u & 0x80000000u) ? ~u : (u | 0x80000000u);
        item[s] = key;
        orig[s] = key;
    }

    // Bitonic sort of 256 u32 keys; position p = lane*8 + s.
#pragma unroll
    for (int ks = 1; ks <= 8; ks++) {
        const int k = 1 << ks;
#pragma unroll
        for (int js = ks - 1; js >= 0; js--) {
            const int j = 1 << js;
            if (j >= 8) {
                const int jl = j >> 3;                       // lane distance
                bool up = ((lane & (k >> 3)) == 0);
                bool keepmin = (((lane & jl) == 0) == up);
#pragma unroll
                for (int s = 0; s < 8; s++) {
                    unsigned o = __shfl_xor_sync(0xffffffffu, item[s], jl);
                    unsigned mn = item[s] < o ? item[s] : o;
                    unsigned mx = item[s] < o ? o : item[s];
                    item[s] = keepmin ? mn : mx;
                }
            } else {
#pragma unroll
                for (int s = 0; s < 8; s++) {
                    if ((s & j) == 0) {
                        int a = s, bb2 = s | j;
                        int p = (lane << 3) | a;
                        bool up = ((p & k) == 0);
                        unsigned xv = item[a], yv = item[bb2];
                        unsigned mn = xv < yv ? xv : yv;
                        unsigned mx = xv < yv ? yv : xv;
                        item[a]   = up ? mn : mx;
                        item[bb2] = up ? mx : mn;
                    }
                }
            }
        }
    }

    // Publish sorted keys (skewed; banks provably distinct per s-slice)
    unsigned* sbuf = sortbuf[warp];
#pragma unroll
    for (int s = 0; s < 8; s++) sbuf[SKW(lane * 8 + s)] = item[s];
    __syncwarp();

    // rank = lower_bound position (keys unique): 8-step binary search, ILP x8
    unsigned lo[8];
#pragma unroll
    for (int s = 0; s < 8; s++) lo[s] = 0;
#pragma unroll
    for (int wstep = 128; wstep > 0; wstep >>= 1) {
#pragma unroll
        for (int s = 0; s < 8; s++) {
            unsigned probe = lo[s] + wstep - 1;
            if (sbuf[SKW(probe)] < orig[s]) lo[s] += wstep;
        }
    }
    __syncwarp();   // done reading sbuf; reuse it as bf16 staging

    __nv_bfloat16* stage = (__nv_bfloat16*)sbuf;
#pragma unroll
    for (int s = 0; s < 8; s++)
        stage[s * 32 + lane] = __float2bfloat16((float)(2 * (int)lo[s] - 255));
    __syncwarp();

    size_t base = (size_t)row * D_DIM;
    uint4 v = ((const uint4*)stage)[lane];          // 8 bf16 per lane
    *(uint4*)(g_c2 + base + lane * 8) = v;
}

// ---------------------------------------------------------------------------
// K2: per-batch S = c2 * c2^T (bf16 mma.sync, fp32 accum, exact).
// Symmetry: only tiles jt >= it (36 of 64); mirror written via smem transpose.
// cp.async 4-chunk K pipeline (K=64 per chunk) hides the tile load.
// Diagonal tiles alias Bs = As (half the loads).
// Epilogue: adj = |S| * 0.25 / (norm^2 + 1e-8).
// ---------------------------------------------------------------------------
#define LDA 264   // padded row length (bf16 elems) to dodge bank conflicts
#define TSP 132   // transpose staging pitch (floats)

__constant__ int IT_MAP[36] = {0,0,0,0,0,0,0,0, 1,1,1,1,1,1,1, 2,2,2,2,2,2,
                               3,3,3,3,3, 4,4,4,4, 5,5,5, 6,6, 7};
__constant__ int JT_MAP[36] = {0,1,2,3,4,5,6,7, 1,2,3,4,5,6,7, 2,3,4,5,6,7,
                               3,4,5,6,7, 4,5,6,7, 5,6,7, 6,7, 7};

__device__ __forceinline__ unsigned sptr(const void* p) {
    return (unsigned)__cvta_generic_to_shared(p);
}
__device__ __forceinline__ void cpasync16(unsigned dst, const void* src) {
    asm volatile("cp.async.cg.shared.global [%0], [%1], 16;\n"
                 :: "r"(dst), "l"(src));
}
__device__ __forceinline__ void cpcommit() {
    asm volatile("cp.async.commit_group;\n");
}
template <int N>
__device__ __forceinline__ void cpwait() {
    asm volatile("cp.async.wait_group %0;\n" :: "n"(N));
}
__device__ __forceinline__ void ldm4(unsigned& r0, unsigned& r1, unsigned& r2,
                                     unsigned& r3, unsigned a) {
    asm volatile("ldmatrix.sync.aligned.m8n8.x4.shared.b16 {%0,%1,%2,%3}, [%4];\n"
                 : "=r"(r0), "=r"(r1), "=r"(r2), "=r"(r3) : "r"(a));
}
__device__ __forceinline__ void mma16816(float* d, const unsigned* a,
                                         unsigned b0, unsigned b1) {
    asm volatile(
        "mma.sync.aligned.m16n8k16.row.col.f32.bf16.bf16.f32 "
        "{%0,%1,%2,%3},{%4,%5,%6,%7},{%8,%9},{%0,%1,%2,%3};\n"
        : "+f"(d[0]), "+f"(d[1]), "+f"(d[2]), "+f"(d[3])
        : "r"(a[0]), "r"(a[1]), "r"(a[2]), "r"(a[3]), "r"(b0), "r"(b1));
}

__global__ __launch_bounds__(256) void k2_gemm(float* __restrict__ out)
{
    extern __shared__ __nv_bfloat16 smem[];
    __nv_bfloat16* As = smem;

    int b = blockIdx.z;
    int tt = blockIdx.x;
    int it = IT_MAP[tt], jt = JT_MAP[tt];
    bool diag = (it == jt);
    __nv_bfloat16* Bs = diag ? As : (smem + 128 * LDA);

    const __nv_bfloat16* Ag = g_c2 + ((size_t)b * N_DIM + it * 128) * D_DIM;
    const __nv_bfloat16* Bg = g_c2 + ((size_t)b * N_DIM + jt * 128) * D_DIM;

    int tid = threadIdx.x;
    // 4 K-chunks of 64 cols; per chunk per matrix: 128 rows x 8 16B-lines.
#pragma unroll
    for (int c = 0; c < 4; c++) {
#pragma unroll
        for (int i = 0; i < 4; i++) {
            int idx = tid + i * 256;             // 0..1023
            int r = idx >> 3, col = idx & 7;     // row, 16B-line in chunk
            int off = c * 64 + col * 8;          // bf16 col offset
            cpasync16(sptr(As + r * LDA + off), Ag + r * D_DIM + off);
        }
        if (!diag) {
#pragma unroll
            for (int i = 0; i < 4; i++) {
                int idx = tid + i * 256;
                int r = idx >> 3, col = idx & 7;
                int off = c * 64 + col * 8;
                cpasync16(sptr(Bs + r * LDA + off), Bg + r * D_DIM + off);
            }
        }
        cpcommit();
    }

    int wid = tid >> 5, lane = tid & 31;
    int wm = (wid >> 2) * 64, wn = (wid & 3) * 32;

    float acc[4][4][4];
#pragma unroll
    for (int mf = 0; mf < 4; mf++)
#pragma unroll
        for (int nf = 0; nf < 4; nf++)
#pragma unroll
            for (int r = 0; r < 4; r++) acc[mf][nf][r] = 0.f;

    unsigned aaddr[4];
#pragma unroll
    for (int mf = 0; mf < 4; mf++)
        aaddr[mf] = sptr(As + (wm + mf * 16 + (lane & 15)) * LDA + ((lane >> 4) << 3));
    unsigned baddr = sptr(Bs + (wn + lane) * LDA);

#pragma unroll
    for (int c = 0; c < 4; c++) {
        if (c == 0) cpwait<3>();
        else if (c == 1) cpwait<2>();
        else if (c == 2) cpwait<1>();
        else cpwait<0>();
        __syncthreads();
#pragma unroll
        for (int kk = 0; kk < 64; kk += 16) {
            int k = c * 64 + kk;
            unsigned a[4][4];
#pragma unroll
            for (int mf = 0; mf < 4; mf++)
                ldm4(a[mf][0], a[mf][1], a[mf][2], a[mf][3], aaddr[mf] + 2 * k);
            unsigned bl[4], bh[4];
            ldm4(bl[0], bl[1], bl[2], bl[3], baddr + 2 * k);
            ldm4(bh[0], bh[1], bh[2], bh[3], baddr + 2 * k + 16);
#pragma unroll
            for (int mf = 0; mf < 4; mf++)
#pragma unroll
                for (int nf = 0; nf < 4; nf++)
                    mma16816(acc[mf][nf], a[mf], bl[nf], bh[nf]);
        }
    }

    // adj = |S/4| / (norm^2 + 1e-8), norm = sqrt(1398080) (constant)
    const float nn = sqrtf(1398080.0f);
    const float scale = 0.25f / (nn * nn + 1e-8f);

    int il = wm + (lane >> 2);          // local i of fragment row 0
    int jl = wn + (lane & 3) * 2;       // local j of fragment col 0
    float* ob = out + (size_t)b * N_DIM * N_DIM;

    float vabs[4][4][4];
#pragma unroll
    for (int mf = 0; mf < 4; mf++)
#pragma unroll
        for (int nf = 0; nf < 4; nf++)
#pragma unroll
            for (int r = 0; r < 4; r++)
                vabs[mf][nf][r] = fabsf(acc[mf][nf][r]) * scale;

    // direct (upper) tile write, coalesced
#pragma unroll
    for (int mf = 0; mf < 4; mf++)
#pragma unroll
        for (int nf = 0; nf < 4; nf++) {
            int i0 = it * 128 + il + mf * 16, j0 = jt * 128 + jl + nf * 8;
            float2 v0, v1;
            v0.x = vabs[mf][nf][0]; v0.y = vabs[mf][nf][1];
            v1.x = vabs[mf][nf][2]; v1.y = vabs[mf][nf][3];
            *(float2*)(ob + (size_t)i0 * N_DIM + j0) = v0;
            *(float2*)(ob + (size_t)(i0 + 8) * N_DIM + j0) = v1;
        }

    if (diag) return;

    // mirror tile: stage transposed in smem (pitch 132 -> conflict-free)
    __syncthreads();            // all warps done reading As/Bs
    float* ts = (float*)smem;   // ts[j*TSP + i] holds adj(i,j)
#pragma unroll
    for (int mf = 0; mf < 4; mf++)
#pragma unroll
        for (int nf = 0; nf < 4; nf++) {
            int i0 = il + mf * 16, j0 = jl + nf * 8;
            ts[(j0    ) * TSP + i0    ] = vabs[mf][nf][0];
            ts[(j0 + 1) * TSP + i0    ] = vabs[mf][nf][1];
            ts[(j0    ) * TSP + i0 + 8] = vabs[mf][nf][2];
            ts[(j0 + 1) * TSP + i0 + 8] = vabs[mf][nf][3];
        }
    __syncthreads();

    // write lower tile (jt,it): row r (j-local), cols i-local, coalesced
#pragma unroll
    for (int pass = 0; pass < 16; pass++) {
        int r = (tid >> 5) + pass * 8;
        int c4 = (tid & 31) * 4;
        float4 v = *(float4*)&ts[r * TSP + c4];
        *(float4*)(ob + (size_t)(jt * 128 + r) * N_DIM + it * 128 + c4) = v;
    }
}

// ---------------------------------------------------------------------------
// K3: in-place LayerNorm over last axis (N=1024) + ReLU. One block per row.
// ---------------------------------------------------------------------------
__global__ __launch_bounds__(256) void k3_ln(float* __restrict__ out,
                                             const float* __restrict__ sg,
                                             const float* __restrict__ sb)
{
    size_t row = blockIdx.x;
    float* p = out + row * N_DIM;
    int tid = threadIdx.x;

    float4 v = ((const float4*)p)[tid];
    float s = v.x + v.y + v.z + v.w;
    float q = v.x * v.x + v.y * v.y + v.z * v.z + v.w * v.w;
#pragma unroll
    for (int o = 16; o > 0; o >>= 1) {
        s += __shfl_xor_sync(0xffffffffu, s, o);
        q += __shfl_xor_sync(0xffffffffu, q, o);
    }
    __shared__ float rs[8], rq[8];
    __shared__ float smu, srstd;
    int wid = tid >> 5, lane = tid & 31;
    if (lane == 0) { rs[wid] = s; rq[wid] = q; }
    __syncthreads();
    if (tid == 0) {
        float S = 0.f, Q = 0.f;
#pragma unroll
        for (int i = 0; i < 8; i++) { S += rs[i]; Q += rq[i]; }
        float mu = S * (1.0f / N_DIM);
        float var = Q * (1.0f / N_DIM) - mu * mu;
        smu = mu;
        srstd = rsqrtf(var + 1e-5f);
    }
    __syncthreads();
    float mu = smu, rstd = srstd;

    float4 g = ((const float4*)sg)[tid];
    float4 bb = ((const float4*)sb)[tid];
    float4 r;
    r.x = fmaxf((v.x - mu) * rstd * g.x + bb.x, 0.0f);
    r.y = fmaxf((v.y - mu) * rstd * g.y + bb.y, 0.0f);
    r.z = fmaxf((v.z - mu) * rstd * g.z + bb.z, 0.0f);
    r.w = fmaxf((v.w - mu) * rstd * g.w + bb.w, 0.0f);
    ((float4*)p)[tid] = r;
}

// ---------------------------------------------------------------------------
extern "C" void kernel_launch(void* const* d_in, const int* in_sizes, int n_in,
                              void* d_out, int out_size)
{
    (void)in_sizes; (void)n_in; (void)out_size;
    const float* x        = (const float*)d_in[0];
    const float* conv_w   = (const float*)d_in[1];
    const float* conv_b   = (const float*)d_in[2];
    const float* time_g   = (const float*)d_in[3];
    const float* time_b   = (const float*)d_in[4];
    const float* static_g = (const float*)d_in[5];
    const float* static_b = (const float*)d_in[6];
    float* out = (float*)d_out;

    k1_rank<<<NROWS / 8, 256>>>(x, conv_w, conv_b, time_g, time_b);

    size_t smem_bytes = 2 * 128 * LDA * sizeof(__nv_bfloat16);
    cudaFuncSetAttribute(k2_gemm, cudaFuncAttributeMaxDynamicSharedMemorySize,
                         (int)smem_bytes);
    dim3 g2(36, 1, 64);
    k2_gemm<<<g2, 256, smem_bytes>>>(out);

    k3_ln<<<NROWS, 256>>>(out, static_g, static_b);
}

// round 5
// speedup vs baseline: 3.4292x; 1.1217x over previous
#include <cuda_runtime.h>
#include <cuda_bf16.h>
#include <cstdint>
#include <cstddef>

#define B_DIM 64
#define N_DIM 1024
#define D_DIM 256
#define T_DIM 13
#define C_DIM 2
#define KX (C_DIM * T_DIM)          // 26
#define NROWS (B_DIM * N_DIM)        // 65536

// c2 = 2*rank - 255 per (row, d), exact in bf16. 32 MB static scratch.
__device__ __nv_bfloat16 g_c2[(size_t)NROWS * D_DIM];

// skewed index for per-warp sorted-key buffer (conflict-free binary search)
#define SKW(i) ((i) + ((i) >> 5))
#define SBUF_LEN 264

// ---------------------------------------------------------------------------
// Bitonic sort of 256 u32 keys across a warp; 8 keys/lane, pos p = lane*8+s.
// ---------------------------------------------------------------------------
__device__ __forceinline__ void bitonic256(unsigned item[8], int lane)
{
#pragma unroll
    for (int ks = 1; ks <= 8; ks++) {
        const int k = 1 << ks;
#pragma unroll
        for (int js = ks - 1; js >= 0; js--) {
            const int j = 1 << js;
            if (j >= 8) {
                const int jl = j >> 3;
                bool up = ((lane & (k >> 3)) == 0);
                bool keepmin = (((lane & jl) == 0) == up);
#pragma unroll
                for (int s = 0; s < 8; s++) {
                    unsigned o = __shfl_xor_sync(0xffffffffu, item[s], jl);
                    unsigned mn = item[s] < o ? item[s] : o;
                    unsigned mx = item[s] < o ? o : item[s];
                    item[s] = keepmin ? mn : mx;
                }
            } else {
#pragma unroll
                for (int s = 0; s < 8; s++) {
                    if ((s & j) == 0) {
                        int a = s, b2 = s | j;
                        int p = (lane << 3) | a;
                        bool up = ((p & k) == 0);
                        unsigned xv = item[a], yv = item[b2];
                        unsigned mn = xv < yv ? xv : yv;
                        unsigned mx = xv < yv ? yv : xv;
                        item[a]  = up ? mn : mx;
                        item[b2] = up ? mx : mn;
                    }
                }
            }
        }
    }
}

// ---------------------------------------------------------------------------
// K1: conv (26-dot) + LayerNorm(D) + rank via 32-bit warp bitonic sort +
// skewed-smem binary search. TWO rows per warp: weight LDS amortized 2x.
// ---------------------------------------------------------------------------
__global__ __launch_bounds__(256) void k1_rank(
    const float* __restrict__ x, const float* __restrict__ w,
    const float* __restrict__ cb, const float* __restrict__ tg,
    const float* __restrict__ tb)
{
    __shared__ float wst[KX * D_DIM];          // weights transposed [k][d]
    __shared__ float scb[D_DIM];
    __shared__ float sxs[16][KX + 2];
    __shared__ unsigned sortbuf[16][SBUF_LEN]; // per-row sorted keys (skewed)

    int tid = threadIdx.x;
#pragma unroll
    for (int k = 0; k < KX; k++) wst[k * D_DIM + tid] = w[tid * KX + k];
    scb[tid] = cb[tid];

    int warp = tid >> 5, lane = tid & 31;
    int row0 = blockIdx.x * 16 + warp * 2;

#pragma unroll
    for (int r = 0; r < 2; r++) {
        int row = row0 + r;
        int b = row >> 10, n = row & 1023;
        if (lane < KX) {
            int c = lane / T_DIM, t = lane - c * T_DIM;
            sxs[warp * 2 + r][lane] =
                x[(((size_t)b * C_DIM + c) * N_DIM + n) * T_DIM + t];
        }
    }
    __syncthreads();

    // per-lane LN affine params from global (L1-cached, same for all warps)
    float gv[8], bv[8];
#pragma unroll
    for (int s = 0; s < 8; s++) { gv[s] = tg[s * 32 + lane]; bv[s] = tb[s * 32 + lane]; }

    // conv for both rows; weight LDS shared
    float e0[8], e1[8];
#pragma unroll
    for (int s = 0; s < 8; s++) { e0[s] = scb[s * 32 + lane]; e1[s] = e0[s]; }
#pragma unroll
    for (int k = 0; k < KX; k++) {
        float x0 = sxs[warp * 2][k], x1 = sxs[warp * 2 + 1][k];
#pragma unroll
        for (int s = 0; s < 8; s++) {
            float wv = wst[k * D_DIM + s * 32 + lane];
            e0[s] += x0 * wv;
            e1[s] += x1 * wv;
        }
    }

    // LayerNorm stats, both rows interleaved
    float s0 = 0.f, q0 = 0.f, s1 = 0.f, q1 = 0.f;
#pragma unroll
    for (int s = 0; s < 8; s++) {
        s0 += e0[s]; q0 += e0[s] * e0[s];
        s1 += e1[s]; q1 += e1[s] * e1[s];
    }
#pragma unroll
    for (int o = 16; o > 0; o >>= 1) {
        s0 += __shfl_xor_sync(0xffffffffu, s0, o);
        q0 += __shfl_xor_sync(0xffffffffu, q0, o);
        s1 += __shfl_xor_sync(0xffffffffu, s1, o);
        q1 += __shfl_xor_sync(0xffffffffu, q1, o);
    }
    float mu0 = s0 * (1.0f / D_DIM);
    float rstd0 = rsqrtf(q0 * (1.0f / D_DIM) - mu0 * mu0 + 1e-5f);
    float mu1 = s1 * (1.0f / D_DIM);
    float rstd1 = rsqrtf(q1 * (1.0f / D_DIM) - mu1 * mu1 + 1e-5f);

    // monotonic u32 keys
    unsigned orig0[8], orig1[8];
#pragma unroll
    for (int s = 0; s < 8; s++) {
        float z0 = (e0[s] - mu0) * rstd0 * gv[s] + bv[s];
        float z1 = (e1[s] - mu1) * rstd1 * gv[s] + bv[s];
        unsigned u0 = __float_as_uint(z0);
        unsigned u1 = __float_as_uint(z1);
        orig0[s] = (u0 & 0x80000000u) ? ~u0 : (u0 | 0x80000000u);
        orig1[s] = (u1 & 0x80000000u) ? ~u1 : (u1 | 0x80000000u);
    }

    unsigned* sb0 = sortbuf[warp * 2];
    unsigned* sb1 = sortbuf[warp * 2 + 1];

    {   // sort row0, publish
        unsigned item[8];
#pragma unroll
        for (int s = 0; s < 8; s++) item[s] = orig0[s];
        bitonic256(item, lane);
#pragma unroll
        for (int s = 0; s < 8; s++) sb0[SKW(lane * 8 + s)] = item[s];
    }
    {   // sort row1, publish
        unsigned item[8];
#pragma unroll
        for (int s = 0; s < 8; s++) item[s] = orig1[s];
        bitonic256(item, lane);
#pragma unroll
        for (int s = 0; s < 8; s++) sb1[SKW(lane * 8 + s)] = item[s];
    }
    __syncwarp();

    // lower_bound ranks (keys unique w.h.p.), both rows for ILP
    unsigned lo0[8], lo1[8];
#pragma unroll
    for (int s = 0; s < 8; s++) { lo0[s] = 0; lo1[s] = 0; }
#pragma unroll
    for (int wstep = 128; wstep > 0; wstep >>= 1) {
#pragma unroll
        for (int s = 0; s < 8; s++) {
            if (sb0[SKW(lo0[s] + wstep - 1)] < orig0[s]) lo0[s] += wstep;
            if (sb1[SKW(lo1[s] + wstep - 1)] < orig1[s]) lo1[s] += wstep;
        }
    }
    __syncwarp();   // done reading sbufs; reuse as bf16 staging

    __nv_bfloat16* st0 = (__nv_bfloat16*)sb0;
    __nv_bfloat16* st1 = (__nv_bfloat16*)sb1;
#pragma unroll
    for (int s = 0; s < 8; s++) {
        st0[s * 32 + lane] = __float2bfloat16((float)(2 * (int)lo0[s] - 255));
        st1[s * 32 + lane] = __float2bfloat16((float)(2 * (int)lo1[s] - 255));
    }
    __syncwarp();

    size_t base = (size_t)row0 * D_DIM;
    *(uint4*)(g_c2 + base + lane * 8) = ((const uint4*)st0)[lane];
    *(uint4*)(g_c2 + base + D_DIM + lane * 8) = ((const uint4*)st1)[lane];
}

// ---------------------------------------------------------------------------
// K2: per-batch S = c2 * c2^T (bf16 mma.sync, fp32 accum, exact).
// Upper tiles only (36/64); mirror via smem transpose. Double-buffered
// cp.async K-chunks of 64 (pitch 72 bf16 -> ldmatrix conflict-free),
// 73.7KB smem -> 2 CTAs/SM. Epilogue adj = |S|*0.25/(norm^2+1e-8).
// ---------------------------------------------------------------------------
#define LDB 72    // chunk pitch in bf16 (144B rows: LDSM + cp.async CF)
#define TSP 132   // transpose staging pitch (floats)

__constant__ int IT_MAP[36] = {0,0,0,0,0,0,0,0, 1,1,1,1,1,1,1, 2,2,2,2,2,2,
                               3,3,3,3,3, 4,4,4,4, 5,5,5, 6,6, 7};
__constant__ int JT_MAP[36] = {0,1,2,3,4,5,6,7, 1,2,3,4,5,6,7, 2,3,4,5,6,7,
                               3,4,5,6,7, 4,5,6,7, 5,6,7, 6,7, 7};

__device__ __forceinline__ unsigned sptr(const void* p) {
    return (unsigned)__cvta_generic_to_shared(p);
}
__device__ __forceinline__ void cpasync16(unsigned dst, const void* src) {
    asm volatile("cp.async.cg.shared.global [%0], [%1], 16;\n"
                 :: "r"(dst), "l"(src));
}
__device__ __forceinline__ void cpcommit() {
    asm volatile("cp.async.commit_group;\n");
}
template <int N>
__device__ __forceinline__ void cpwait() {
    asm volatile("cp.async.wait_group %0;\n" :: "n"(N));
}
__device__ __forceinline__ void ldm4(unsigned& r0, unsigned& r1, unsigned& r2,
                                     unsigned& r3, unsigned a) {
    asm volatile("ldmatrix.sync.aligned.m8n8.x4.shared.b16 {%0,%1,%2,%3}, [%4];\n"
                 : "=r"(r0), "=r"(r1), "=r"(r2), "=r"(r3) : "r"(a));
}
__device__ __forceinline__ void mma16816(float* d, const unsigned* a,
                                         unsigned b0, unsigned b1) {
    asm volatile(
        "mma.sync.aligned.m16n8k16.row.col.f32.bf16.bf16.f32 "
        "{%0,%1,%2,%3},{%4,%5,%6,%7},{%8,%9},{%0,%1,%2,%3};\n"
        : "+f"(d[0]), "+f"(d[1]), "+f"(d[2]), "+f"(d[3])
        : "r"(a[0]), "r"(a[1]), "r"(a[2]), "r"(a[3]), "r"(b0), "r"(b1));
}

__global__ __launch_bounds__(256, 2) void k2_gemm(float* __restrict__ out)
{
    extern __shared__ __nv_bfloat16 smem[];

    int b = blockIdx.z;
    int tt = blockIdx.x;
    int it = IT_MAP[tt], jt = JT_MAP[tt];
    bool diag = (it == jt);

    __nv_bfloat16* Ast[2] = { smem, smem + 128 * LDB };
    __nv_bfloat16* Bst[2] = { diag ? Ast[0] : smem + 2 * 128 * LDB,
                              diag ? Ast[1] : smem + 3 * 128 * LDB };

    const __nv_bfloat16* Ag = g_c2 + ((size_t)b * N_DIM + it * 128) * D_DIM;
    const __nv_bfloat16* Bg = g_c2 + ((size_t)b * N_DIM + jt * 128) * D_DIM;

    int tid = threadIdx.x;

    // chunk loader: 128 rows x 8 16B-lines per matrix
#define LOAD_CHUNK(c, Ad, Bd)                                                  \
    do {                                                                       \
        _Pragma("unroll")                                                      \
        for (int i = 0; i < 4; i++) {                                          \
            int idx = tid + i * 256;                                           \
            int r = idx >> 3, line = idx & 7;                                  \
            int off = (c) * 64 + line * 8;                                     \
            cpasync16(sptr((Ad) + r * LDB + line * 8), Ag + r * D_DIM + off);  \
        }                                                                      \
        if (!diag) {                                                           \
            _Pragma("unroll")                                                  \
            for (int i = 0; i < 4; i++) {                                      \
                int idx = tid + i * 256;                                       \
                int r = idx >> 3, line = idx & 7;                              \
                int off = (c) * 64 + line * 8;                                 \
                cpasync16(sptr((Bd) + r * LDB + line * 8), Bg + r * D_DIM + off); \
            }                                                                  \
        }                                                                      \
        cpcommit();                                                            \
    } while (0)

    LOAD_CHUNK(0, Ast[0], Bst[0]);
    LOAD_CHUNK(1, Ast[1], Bst[1]);

    int wid = tid >> 5, lane = tid & 31;
    int wm = (wid >> 2) * 64, wn = (wid & 3) * 32;

    float acc[4][4][4];
#pragma unroll
    for (int mf = 0; mf < 4; mf++)
#pragma unroll
        for (int nf = 0; nf < 4; nf++)
#pragma unroll
            for (int r = 0; r < 4; r++) acc[mf][nf][r] = 0.f;

#pragma unroll
    for (int c = 0; c < 4; c++) {
        if (c < 3) cpwait<1>(); else cpwait<0>();
        __syncthreads();
        __nv_bfloat16* Asb = Ast[c & 1];
        __nv_bfloat16* Bsb = Bst[c & 1];
        unsigned aaddr[4];
#pragma unroll
        for (int mf = 0; mf < 4; mf++)
            aaddr[mf] = sptr(Asb + (wm + mf * 16 + (lane & 15)) * LDB
                             + ((lane >> 4) << 3));
        unsigned baddr = sptr(Bsb + (wn + lane) * LDB);

#pragma unroll
        for (int kk = 0; kk < 64; kk += 16) {
            unsigned a[4][4];
#pragma unroll
            for (int mf = 0; mf < 4; mf++)
                ldm4(a[mf][0], a[mf][1], a[mf][2], a[mf][3], aaddr[mf] + 2 * kk);
            unsigned bl[4], bh[4];
            ldm4(bl[0], bl[1], bl[2], bl[3], baddr + 2 * kk);
            ldm4(bh[0], bh[1], bh[2], bh[3], baddr + 2 * kk + 16);
#pragma unroll
            for (int mf = 0; mf < 4; mf++)
#pragma unroll
                for (int nf = 0; nf < 4; nf++)
                    mma16816(acc[mf][nf], a[mf], bl[nf], bh[nf]);
        }
        if (c + 2 < 4) {
            __syncthreads();                 // all warps done reading stage
            LOAD_CHUNK(c + 2, Asb, Bsb);
        }
    }

    const float nn = sqrtf(1398080.0f);
    const float scale = 0.25f / (nn * nn + 1e-8f);

    int il = wm + (lane >> 2);
    int jl = wn + (lane & 3) * 2;
    float* ob = out + (size_t)b * N_DIM * N_DIM;

    // direct (upper) tile write, coalesced
#pragma unroll
    for (int mf = 0; mf < 4; mf++)
#pragma unroll
        for (int nf = 0; nf < 4; nf++) {
            int i0 = it * 128 + il + mf * 16, j0 = jt * 128 + jl + nf * 8;
            float2 v0, v1;
            v0.x = fabsf(acc[mf][nf][0]) * scale;
            v0.y = fabsf(acc[mf][nf][1]) * scale;
            v1.x = fabsf(acc[mf][nf][2]) * scale;
            v1.y = fabsf(acc[mf][nf][3]) * scale;
            *(float2*)(ob + (size_t)i0 * N_DIM + j0) = v0;
            *(float2*)(ob + (size_t)(i0 + 8) * N_DIM + j0) = v1;
        }

    if (diag) return;

    // mirror tile via smem transpose staging (pitch 132 -> conflict-free)
    __syncthreads();
    float* ts = (float*)smem;
#pragma unroll
    for (int mf = 0; mf < 4; mf++)
#pragma unroll
        for (int nf = 0; nf < 4; nf++) {
            int i0 = il + mf * 16, j0 = jl + nf * 8;
            ts[(j0    ) * TSP + i0    ] = fabsf(acc[mf][nf][0]) * scale;
            ts[(j0 + 1) * TSP + i0    ] = fabsf(acc[mf][nf][1]) * scale;
            ts[(j0    ) * TSP + i0 + 8] = fabsf(acc[mf][nf][2]) * scale;
            ts[(j0 + 1) * TSP + i0 + 8] = fabsf(acc[mf][nf][3]) * scale;
        }
    __syncthreads();

#pragma unroll
    for (int pass = 0; pass < 16; pass++) {
        int r = (tid >> 5) + pass * 8;
        int c4 = (tid & 31) * 4;
        float4 v = *(float4*)&ts[r * TSP + c4];
        *(float4*)(ob + (size_t)(jt * 128 + r) * N_DIM + it * 128 + c4) = v;
    }
#undef LOAD_CHUNK
}

// ---------------------------------------------------------------------------
// K3: in-place LayerNorm over last axis (N=1024) + ReLU. One block per row.
// ---------------------------------------------------------------------------
__global__ __launch_bounds__(256) void k3_ln(float* __restrict__ out,
                                             const float* __restrict__ sg,
                                             const float* __restrict__ sb)
{
    size_t row = blockIdx.x;
    float* p = out + row * N_DIM;
    int tid = threadIdx.x;

    float4 v = ((const float4*)p)[tid];
    float s = v.x + v.y + v.z + v.w;
    float q = v.x * v.x + v.y * v.y + v.z * v.z + v.w * v.w;
#pragma unroll
    for (int o = 16; o > 0; o >>= 1) {
        s += __shfl_xor_sync(0xffffffffu, s, o);
        q += __shfl_xor_sync(0xffffffffu, q, o);
    }
    __shared__ float rs[8], rq[8];
    __shared__ float smu, srstd;
    int wid = tid >> 5, lane = tid & 31;
    if (lane == 0) { rs[wid] = s; rq[wid] = q; }
    __syncthreads();
    if (tid == 0) {
        float S = 0.f, Q = 0.f;
#pragma unroll
        for (int i = 0; i < 8; i++) { S += rs[i]; Q += rq[i]; }
        float mu = S * (1.0f / N_DIM);
        float var = Q * (1.0f / N_DIM) - mu * mu;
        smu = mu;
        srstd = rsqrtf(var + 1e-5f);
    }
    __syncthreads();
    float mu = smu, rstd = srstd;

    float4 g = ((const float4*)sg)[tid];
    float4 bb = ((const float4*)sb)[tid];
    float4 r;
    r.x = fmaxf((v.x - mu) * rstd * g.x + bb.x, 0.0f);
    r.y = fmaxf((v.y - mu) * rstd * g.y + bb.y, 0.0f);
    r.z = fmaxf((v.z - mu) * rstd * g.z + bb.z, 0.0f);
    r.w = fmaxf((v.w - mu) * rstd * g.w + bb.w, 0.0f);
    ((float4*)p)[tid] = r;
}

// ---------------------------------------------------------------------------
extern "C" void kernel_launch(void* const* d_in, const int* in_sizes, int n_in,
                              void* d_out, int out_size)
{
    (void)in_sizes; (void)n_in; (void)out_size;
    const float* x        = (const float*)d_in[0];
    const float* conv_w   = (const float*)d_in[1];
    const float* conv_b   = (const float*)d_in[2];
    const float* time_g   = (const float*)d_in[3];
    const float* time_b   = (const float*)d_in[4];
    const float* static_g = (const float*)d_in[5];
    const float* static_b = (const float*)d_in[6];
    float* out = (float*)d_out;

    k1_rank<<<NROWS / 16, 256>>>(x, conv_w, conv_b, time_g, time_b);

    size_t smem_bytes = 4 * 128 * LDB * sizeof(__nv_bfloat16);   // 73728
    cudaFuncSetAttribute(k2_gemm, cudaFuncAttributeMaxDynamicSharedMemorySize,
                         (int)smem_bytes);
    dim3 g2(36, 1, 64);
    k2_gemm<<<g2, 256, smem_bytes>>>(out);

    k3_ln<<<NROWS, 256>>>(out, static_g, static_b);
}